// round 3
// baseline (speedup 1.0000x reference)
#include <cuda_runtime.h>
#include <cstdint>

#define BATCH   16384
#define DIM     128
#define NF      27          // 1 dense + 26 sparse rows
#define OUTW    479         // 128 + 351
#define ROWS    8           // batch rows per CTA
#define THREADS 224         // 8 rows * 28 tiles
#define RSTRIDE 14352       // 28 rows * 512B + 16B pad (de-conflict across batch rows)
#define SMEM_BYTES (ROWS * RSTRIDE)   // 114816

__global__ __launch_bounds__(THREADS, 2)
void dlrm_interact_kernel(const float* __restrict__ dense,
                          const float* __restrict__ sparse,
                          float* __restrict__ out) {
    extern __shared__ char smem[];
    const int tid = threadIdx.x;
    const int b0  = blockIdx.x * ROWS;

    // ---------------- load phase: gmem -> swizzled smem ----------------
    // 28 rows * 32 float4 per batch row (row 27 = zero pad). Coalesced float4 reads.
    // Swizzle: float4 column k4 stored at (k4 ^ (f>>2)) so compute-phase loads,
    // which vary ti=f>>2 across lanes, hit distinct bank groups.
    for (int i = tid; i < ROWS * 28 * 32; i += THREADS) {
        int br  = i / 896;            // 28*32
        int rem = i - br * 896;
        int f   = rem >> 5;
        int k4  = rem & 31;
        int b   = b0 + br;
        float4 v = make_float4(0.f, 0.f, 0.f, 0.f);
        if (f == 0) {
            v = reinterpret_cast<const float4*>(dense)[b * 32 + k4];
            // dense passthrough (out rows are 479 floats -> 4B aligned only)
            float* o = out + (size_t)b * OUTW + (k4 << 2);
            o[0] = v.x; o[1] = v.y; o[2] = v.z; o[3] = v.w;
        } else if (f < NF) {
            v = reinterpret_cast<const float4*>(sparse)[(b * 26 + (f - 1)) * 32 + k4];
        }
        int ks = k4 ^ ((f >> 2) & 7);
        *reinterpret_cast<float4*>(smem + br * RSTRIDE + f * 512 + (ks << 4)) = v;
    }
    __syncthreads();

    // ---------------- compute phase: one 4x4 Gram tile per thread ----------------
    const int br = tid / 28;
    int t  = tid - br * 28;
    int ti = 0;
    while (t >= 7 - ti) { t -= 7 - ti; ti++; }   // enumerate ti<=tj over 7x7 triu
    const int tj = ti + t;

    const char* base = smem + br * RSTRIDE;
    const char* ib   = base + (ti * 4) * 512;
    const char* jb   = base + (tj * 4) * 512;

    // packed-k accumulators: each holds (sum of even k, sum of odd k) as f32x2
    unsigned long long acc[4][4];
#pragma unroll
    for (int r = 0; r < 4; r++)
#pragma unroll
        for (int c = 0; c < 4; c++) acc[r][c] = 0ull;

#pragma unroll 4
    for (int k4 = 0; k4 < 32; k4++) {
        const int oi = (k4 ^ ti) << 4;
        const int oj = (k4 ^ tj) << 4;
        ulonglong2 ai[4], aj[4];
#pragma unroll
        for (int r = 0; r < 4; r++)
            ai[r] = *reinterpret_cast<const ulonglong2*>(ib + r * 512 + oi);
#pragma unroll
        for (int c = 0; c < 4; c++)
            aj[c] = *reinterpret_cast<const ulonglong2*>(jb + c * 512 + oj);
#pragma unroll
        for (int r = 0; r < 4; r++)
#pragma unroll
            for (int c = 0; c < 4; c++) {
                // packed fp32x2 FMA: 2 fp32 FMAs per instruction, operands come
                // straight from the LDS.128 register quads (no pack MOVs)
                asm("fma.rn.f32x2 %0, %1, %2, %0;"
                    : "+l"(acc[r][c]) : "l"(ai[r].x), "l"(aj[c].x));
                asm("fma.rn.f32x2 %0, %1, %2, %0;"
                    : "+l"(acc[r][c]) : "l"(ai[r].y), "l"(aj[c].y));
            }
    }

    // ---------------- epilogue: reduce packed halves, scatter triu pairs ----------------
    const int b = b0 + br;
    float* orow = out + (size_t)b * OUTW + DIM;
#pragma unroll
    for (int r = 0; r < 4; r++) {
        const int fi = ti * 4 + r;
#pragma unroll
        for (int c = 0; c < 4; c++) {
            const int fj = tj * 4 + c;
            if (fi < fj && fj < NF) {
                float lo, hi;
                asm("mov.b64 {%0, %1}, %2;" : "=f"(lo), "=f"(hi) : "l"(acc[r][c]));
                // pair index for triu_indices(27, k=1), row-major
                const int p = fi * 26 - (fi * (fi - 1)) / 2 + (fj - fi - 1);
                orow[p] = lo + hi;
            }
        }
    }
}

extern "C" void kernel_launch(void* const* d_in, const int* in_sizes, int n_in,
                              void* d_out, int out_size) {
    const float* dense  = (const float*)d_in[0];   // [16384, 128] fp32
    const float* sparse = (const float*)d_in[1];   // [16384, 26, 128] fp32
    float* out = (float*)d_out;                    // [16384, 479] fp32

    cudaFuncSetAttribute(dlrm_interact_kernel,
                         cudaFuncAttributeMaxDynamicSharedMemorySize, SMEM_BYTES);
    dlrm_interact_kernel<<<BATCH / ROWS, THREADS, SMEM_BYTES>>>(dense, sparse, out);
}

// round 4
// speedup vs baseline: 1.0783x; 1.0783x over previous
#include <cuda_runtime.h>
#include <cstdint>

#define BATCH   16384
#define DIM     128
#define NF      27          // 1 dense + 26 sparse rows
#define OUTW    479         // 128 + 351
#define SAMPLES 8           // batch rows per CTA (one warp each)
#define THREADS 256
#define SSTRIDE 14336       // 28 rows * 512 B per sample
#define SMEM_BYTES (SAMPLES * SSTRIDE)   // 114688 -> 2 CTAs/SM

__global__ __launch_bounds__(THREADS, 2)
void dlrm_interact_kernel(const float* __restrict__ dense,
                          const float* __restrict__ sparse,
                          float* __restrict__ out) {
    extern __shared__ char smem[];
    const int tid = threadIdx.x;
    const int b0  = blockIdx.x * SAMPLES;

    // ---------------- load phase: gmem -> swizzled smem ----------------
    // 8 samples * 28 rows * 32 float4 (row 27 = zero pad). Coalesced float4 reads:
    // 32 consecutive tids cover k4=0..31 of one (s,f) row.
    // Swizzle: float4 chunk k4 of row f stored at chunk (k4 ^ (f>>2)) so that
    // compute-phase loads (lanes vary ti=f>>2) hit distinct 16B bank groups.
    for (int i = tid; i < SAMPLES * 28 * 32; i += THREADS) {
        int s   = i / 896;            // 28*32
        int rem = i - s * 896;
        int f   = rem >> 5;
        int k4  = rem & 31;
        int b   = b0 + s;
        float4 v = make_float4(0.f, 0.f, 0.f, 0.f);
        if (f == 0) {
            v = reinterpret_cast<const float4*>(dense)[b * 32 + k4];
            // dense passthrough (out rows are 479 floats -> only 4B aligned)
            float* o = out + (size_t)b * OUTW + (k4 << 2);
            o[0] = v.x; o[1] = v.y; o[2] = v.z; o[3] = v.w;
        } else if (f < NF) {
            v = reinterpret_cast<const float4*>(sparse)[(b * 26 + (f - 1)) * 32 + k4];
        }
        int ks = k4 ^ ((f >> 2) & 7);
        *reinterpret_cast<float4*>(smem + s * SSTRIDE + f * 512 + (ks << 4)) = v;
    }
    __syncthreads();

    // ---------------- compute phase: warp = sample, one 4x4 tile/lane ----------------
    const int s    = tid >> 5;          // sample = warp
    const int lane = tid & 31;
    int t  = (lane < 28) ? lane : 0;    // lanes 28-31 duplicate tile 0 (broadcast, free)
    int ti = 0;
    while (t >= 7 - ti) { t -= 7 - ti; ti++; }   // enumerate ti<=tj over 7x7 triu
    const int tj = ti + t;

    const char* base = smem + s * SSTRIDE;
    const char* ib   = base + ti * 2048;
    const char* jb   = base + tj * 2048;
    const int ti16 = ti << 4;
    const int tj16 = tj << 4;

    // packed-k accumulators: (sum of even k, sum of odd k) as f32x2
    unsigned long long acc[4][4];
#pragma unroll
    for (int r = 0; r < 4; r++)
#pragma unroll
        for (int c = 0; c < 4; c++) acc[r][c] = 0ull;

#pragma unroll 8
    for (int k4 = 0; k4 < 32; k4++) {
        const int k16 = k4 << 4;
        const char* pi = ib + (k16 ^ ti16);   // 2 ALU ops/iter total for addressing
        const char* pj = jb + (k16 ^ tj16);
        ulonglong2 ai[4], aj[4];
#pragma unroll
        for (int r = 0; r < 4; r++)
            ai[r] = *reinterpret_cast<const ulonglong2*>(pi + r * 512);
#pragma unroll
        for (int c = 0; c < 4; c++)
            aj[c] = *reinterpret_cast<const ulonglong2*>(pj + c * 512);
#pragma unroll
        for (int r = 0; r < 4; r++)
#pragma unroll
            for (int c = 0; c < 4; c++) {
                // packed fp32x2 FMA straight off the LDS.128 register quads
                asm("fma.rn.f32x2 %0, %1, %2, %0;"
                    : "+l"(acc[r][c]) : "l"(ai[r].x), "l"(aj[c].x));
                asm("fma.rn.f32x2 %0, %1, %2, %0;"
                    : "+l"(acc[r][c]) : "l"(ai[r].y), "l"(aj[c].y));
            }
    }

    // ---------------- epilogue: reduce packed halves, scatter triu pairs ----------------
    if (lane < 28) {
        const int b = b0 + s;
        float* orow = out + (size_t)b * OUTW + DIM;
#pragma unroll
        for (int r = 0; r < 4; r++) {
            const int fi = ti * 4 + r;
#pragma unroll
            for (int c = 0; c < 4; c++) {
                const int fj = tj * 4 + c;
                if (fi < fj && fj < NF) {
                    float lo, hi;
                    asm("mov.b64 {%0, %1}, %2;" : "=f"(lo), "=f"(hi) : "l"(acc[r][c]));
                    // pair index for triu_indices(27, k=1), row-major
                    const int p = fi * 26 - (fi * (fi - 1)) / 2 + (fj - fi - 1);
                    orow[p] = lo + hi;
                }
            }
        }
    }
}

extern "C" void kernel_launch(void* const* d_in, const int* in_sizes, int n_in,
                              void* d_out, int out_size) {
    const float* dense  = (const float*)d_in[0];   // [16384, 128] fp32
    const float* sparse = (const float*)d_in[1];   // [16384, 26, 128] fp32
    float* out = (float*)d_out;                    // [16384, 479] fp32

    cudaFuncSetAttribute(dlrm_interact_kernel,
                         cudaFuncAttributeMaxDynamicSharedMemorySize, SMEM_BYTES);
    dlrm_interact_kernel<<<BATCH / SAMPLES, THREADS, SMEM_BYTES>>>(dense, sparse, out);
}

// round 5
// speedup vs baseline: 1.3240x; 1.2279x over previous
#include <cuda_runtime.h>
#include <cstdint>

#define BATCH    16384
#define DIM      128
#define NF       27          // 1 dense + 26 sparse rows
#define OUTW     479         // 128 + 351
#define SAMPLES  8           // samples per CTA
#define WARPS    16          // 8 samples x 2 k-halves
#define THREADS  512
#define HROW     256         // bytes per row per k-half (64 floats)
#define HSTRIDE  7168        // 28 rows * 256 B  (one sample-half)
#define SSTRIDE  14336       // 2 halves
#define SMEM_BYTES (SAMPLES * SSTRIDE)   // 114688 -> 2 CTAs/SM -> 32 warps/SM

__global__ __launch_bounds__(THREADS, 2)
void dlrm_interact_kernel(const float* __restrict__ dense,
                          const float* __restrict__ sparse,
                          float* __restrict__ out) {
    extern __shared__ char smem[];
    const int tid  = threadIdx.x;
    const int w    = tid >> 5;
    const int lane = tid & 31;
    const int s    = w >> 1;          // sample within CTA
    const int half = w & 1;           // k-half: 0 -> k[0,64), 1 -> k[64,128)
    const int b    = blockIdx.x * SAMPLES + s;

    char* sbase = smem + s * SSTRIDE + half * HSTRIDE;

    // ---------------- load phase: warp loads its own sample-half ----------------
    // lane = r2*16 + k4 : chunk k4 (16B) of rows f = 2t + r2, t = 0..13 (f up to 27
    // = zero pad). Coalesced: 16 lanes cover one contiguous 256 B half-row.
    {
        const int k4 = lane & 15;
        const int r2 = lane >> 4;
        const int gchunk = half * 16 + k4;            // float4 index within a 128-f row
#pragma unroll
        for (int t = 0; t < 14; t++) {
            const int f = 2 * t + r2;
            float4 v = make_float4(0.f, 0.f, 0.f, 0.f);
            if (f == 0) {
                v = reinterpret_cast<const float4*>(dense)[b * 32 + gchunk];
                float* o = out + (size_t)b * OUTW + (gchunk << 2);   // passthrough
                o[0] = v.x; o[1] = v.y; o[2] = v.z; o[3] = v.w;
            } else if (f < NF) {
                v = reinterpret_cast<const float4*>(sparse)[(b * 26 + (f - 1)) * 32 + gchunk];
            }
            *reinterpret_cast<float4*>(sbase + f * HROW + ((k4 ^ (f >> 2)) << 4)) = v;
        }
    }
    __syncthreads();

    // ---------------- compute: one 4x4 Gram tile per lane, over this k-half ----------------
    int t  = (lane < 28) ? lane : 0;      // lanes 28-31 shadow tile 0 (broadcast, free)
    int ti = 0;
    while (t >= 7 - ti) { t -= 7 - ti; ti++; }    // ti<=tj over 7x7 triu
    const int tj = ti + t;

    const char* ib = sbase + ti * (4 * HROW);
    const char* jb = sbase + tj * (4 * HROW);
    const int ti16 = ti << 4, tj16 = tj << 4;

    unsigned long long acc[4][4];   // f32x2 packed (even-k sum, odd-k sum)
#pragma unroll
    for (int r = 0; r < 4; r++)
#pragma unroll
        for (int c = 0; c < 4; c++) acc[r][c] = 0ull;

#pragma unroll 8
    for (int k4 = 0; k4 < 16; k4++) {
        const int k16 = k4 << 4;
        const char* pi = ib + (k16 ^ ti16);
        const char* pj = jb + (k16 ^ tj16);
        ulonglong2 ai[4], aj[4];
#pragma unroll
        for (int r = 0; r < 4; r++)
            ai[r] = *reinterpret_cast<const ulonglong2*>(pi + r * HROW);
#pragma unroll
        for (int c = 0; c < 4; c++)
            aj[c] = *reinterpret_cast<const ulonglong2*>(pj + c * HROW);
#pragma unroll
        for (int r = 0; r < 4; r++)
#pragma unroll
            for (int c = 0; c < 4; c++) {
                asm("fma.rn.f32x2 %0, %1, %2, %0;"
                    : "+l"(acc[r][c]) : "l"(ai[r].x), "l"(aj[c].x));
                asm("fma.rn.f32x2 %0, %1, %2, %0;"
                    : "+l"(acc[r][c]) : "l"(ai[r].y), "l"(aj[c].y));
            }
    }

    // reduce packed halves -> 16 scalars per lane
    float val[16];
#pragma unroll
    for (int r = 0; r < 4; r++)
#pragma unroll
        for (int c = 0; c < 4; c++) {
            float lo, hi;
            asm("mov.b64 {%0, %1}, %2;" : "=f"(lo), "=f"(hi) : "l"(acc[r][c]));
            val[r * 4 + c] = lo + hi;
        }

    // ---------------- combine k-halves + scatter ----------------
    // half-1 warp parks partials in its sample's (now dead) tile area; half-0 adds.
    float* cbuf = reinterpret_cast<float*>(smem + s * SSTRIDE);   // 28*16 floats
    __syncthreads();                      // all tile reads done
    if (half == 1 && lane < 28) {
#pragma unroll
        for (int i = 0; i < 16; i++) cbuf[lane * 16 + i] = val[i];
    }
    __syncthreads();
    if (half == 0 && lane < 28) {
        float* orow = out + (size_t)b * OUTW + DIM;
#pragma unroll
        for (int r = 0; r < 4; r++) {
            const int fi = ti * 4 + r;
#pragma unroll
            for (int c = 0; c < 4; c++) {
                const int fj = tj * 4 + c;
                if (fi < fj && fj < NF) {
                    const float v = val[r * 4 + c] + cbuf[lane * 16 + r * 4 + c];
                    // pair index for triu_indices(27, k=1), row-major
                    const int p = fi * 26 - (fi * (fi - 1)) / 2 + (fj - fi - 1);
                    orow[p] = v;
                }
            }
        }
    }
}

extern "C" void kernel_launch(void* const* d_in, const int* in_sizes, int n_in,
                              void* d_out, int out_size) {
    const float* dense  = (const float*)d_in[0];   // [16384, 128] fp32
    const float* sparse = (const float*)d_in[1];   // [16384, 26, 128] fp32
    float* out = (float*)d_out;                    // [16384, 479] fp32

    cudaFuncSetAttribute(dlrm_interact_kernel,
                         cudaFuncAttributeMaxDynamicSharedMemorySize, SMEM_BYTES);
    dlrm_interact_kernel<<<BATCH / SAMPLES, THREADS, SMEM_BYTES>>>(dense, sparse, out);
}

// round 6
// speedup vs baseline: 1.5123x; 1.1422x over previous
#include <cuda_runtime.h>
#include <cstdint>

#define BATCH    16384
#define DIM      128
#define NF       27          // 1 dense + 26 sparse rows
#define OUTW     479         // 128 + 351
#define SAMPLES  8           // samples per CTA
#define THREADS  512         // 16 warps = 8 samples x 2 k-halves
#define HROW     256         // bytes per row per k-half (64 floats)
#define HSTRIDE  7168        // 28 rows * 256 B (one sample-half)
#define SSTRIDE  14336       // 2 halves
#define SMEM_BYTES (SAMPLES * SSTRIDE)   // 114688 -> 2 CTAs/SM -> 32 warps/SM
// overlay buffers (relative to sample region): rows 4..27 of half-0 are dead
// after compute; rows 0-3 (dense, unswizzled in row 0) stay live for copy-out.
#define CBUF_OFF   1024              // 16*32 floats = 2048 B
#define STAGE_OFF  (1024 + 2048)     // 351 floats = 1404 B

__global__ __launch_bounds__(THREADS, 2)
void dlrm_interact_kernel(const float* __restrict__ dense,
                          const float* __restrict__ sparse,
                          float* __restrict__ out) {
    extern __shared__ char smem[];
    const int tid  = threadIdx.x;
    const int w    = tid >> 5;
    const int lane = tid & 31;
    const int s    = w >> 1;          // sample within CTA
    const int half = w & 1;           // k-half: 0 -> k[0,64), 1 -> k[64,128)
    const int b    = blockIdx.x * SAMPLES + s;

    char* srow  = smem + s * SSTRIDE;        // sample region
    char* sbase = srow + half * HSTRIDE;     // this warp's k-half

    // ---------------- load: warp loads its own sample-half (no CTA sync) ----------
    // lane = r2*16 + k4: 16B chunk k4 of rows f = 2t + r2. 32 lanes cover two
    // adjacent rows = 512 contiguous gmem bytes -> 4 wavefronts per LDG.
    {
        const int k4 = lane & 15;
        const int r2 = lane >> 4;
        const int gchunk = half * 16 + k4;          // float4 index within 128-f row
#pragma unroll
        for (int t = 0; t < 14; t++) {
            const int f = 2 * t + r2;
            float4 v = make_float4(0.f, 0.f, 0.f, 0.f);
            if (f == 0)
                v = reinterpret_cast<const float4*>(dense)[b * 32 + gchunk];
            else if (f < NF)
                v = reinterpret_cast<const float4*>(sparse)[(b * 26 + (f - 1)) * 32 + gchunk];
            // swizzle: chunk k4 of row f stored at chunk (k4 ^ (f>>2))
            *reinterpret_cast<float4*>(sbase + f * HROW + ((k4 ^ (f >> 2)) << 4)) = v;
        }
    }
    __syncwarp();   // compute reads only this warp's own half

    // ---------------- compute: one 4x4 Gram tile per lane over this k-half --------
    int t  = (lane < 28) ? lane : 0;      // lanes 28-31 shadow tile 0 (broadcast)
    int ti = 0;
    while (t >= 7 - ti) { t -= 7 - ti; ti++; }    // ti<=tj over 7x7 triu
    const int tj = ti + t;

    const char* ib = sbase + ti * (4 * HROW);
    const char* jb = sbase + tj * (4 * HROW);
    const int ti16 = ti << 4, tj16 = tj << 4;

    unsigned long long acc[4][4];   // f32x2 packed (even-k sum, odd-k sum)
#pragma unroll
    for (int r = 0; r < 4; r++)
#pragma unroll
        for (int c = 0; c < 4; c++) acc[r][c] = 0ull;

#pragma unroll 8
    for (int k4 = 0; k4 < 16; k4++) {
        const int k16 = k4 << 4;
        const char* pi = ib + (k16 ^ ti16);
        const char* pj = jb + (k16 ^ tj16);
        ulonglong2 ai[4], aj[4];
#pragma unroll
        for (int r = 0; r < 4; r++)
            ai[r] = *reinterpret_cast<const ulonglong2*>(pi + r * HROW);
#pragma unroll
        for (int c = 0; c < 4; c++)
            aj[c] = *reinterpret_cast<const ulonglong2*>(jb == ib ? pi + c * HROW : pj + c * HROW);
#pragma unroll
        for (int r = 0; r < 4; r++)
#pragma unroll
            for (int c = 0; c < 4; c++) {
                asm("fma.rn.f32x2 %0, %1, %2, %0;"
                    : "+l"(acc[r][c]) : "l"(ai[r].x), "l"(aj[c].x));
                asm("fma.rn.f32x2 %0, %1, %2, %0;"
                    : "+l"(acc[r][c]) : "l"(ai[r].y), "l"(aj[c].y));
            }
    }

    // reduce packed halves -> 16 scalars per lane
    float val[16];
#pragma unroll
    for (int r = 0; r < 4; r++)
#pragma unroll
        for (int c = 0; c < 4; c++) {
            float lo, hi;
            asm("mov.b64 {%0, %1}, %2;" : "=f"(lo), "=f"(hi) : "l"(acc[r][c]));
            val[r * 4 + c] = lo + hi;
        }

    // ---------------- warp-pair combine + staging (named barriers, 64 threads) ----
    float* cbuf  = reinterpret_cast<float*>(srow + CBUF_OFF);
    float* stage = reinterpret_cast<float*>(srow + STAGE_OFF);
    const int bar = s + 1;

    asm volatile("bar.sync %0, 64;" :: "r"(bar) : "memory");  // both halves done computing
    if (half == 1 && lane < 28) {
#pragma unroll
        for (int i = 0; i < 16; i++)
            cbuf[i * 32 + lane] = val[i];        // stride-1 across lanes: conflict-free
    }
    asm volatile("bar.sync %0, 64;" :: "r"(bar) : "memory");
    if (half == 0 && lane < 28) {
#pragma unroll
        for (int r = 0; r < 4; r++) {
            const int fi = ti * 4 + r;
#pragma unroll
            for (int c = 0; c < 4; c++) {
                const int fj = tj * 4 + c;
                if (fi < fj && fj < NF) {
                    // pair index for triu_indices(27, k=1), row-major
                    const int p = fi * 26 - (fi * (fi - 1)) / 2 + (fj - fi - 1);
                    stage[p] = val[r * 4 + c] + cbuf[(r * 4 + c) * 32 + lane];
                }
            }
        }
    }
    asm volatile("bar.sync %0, 64;" :: "r"(bar) : "memory");

    // ---------------- coalesced copy-out of the full 479-float row ----------------
    // dense k[0,64) sits unswizzled at srow (row 0, half 0), k[64,128) at srow+HSTRIDE.
    const float* d0 = reinterpret_cast<const float*>(srow);
    const float* d1 = reinterpret_cast<const float*>(srow + HSTRIDE);
    float* orow = out + (size_t)b * OUTW;
    const int lid = half * 32 + lane;          // 0..63 within the sample pair
#pragma unroll
    for (int it = 0; it < 8; it++) {
        const int i = lid + it * 64;
        if (i < OUTW) {
            float v;
            if (i < 64)       v = d0[i];
            else if (i < 128) v = d1[i - 64];
            else              v = stage[i - 128];
            orow[i] = v;
        }
    }
}

extern "C" void kernel_launch(void* const* d_in, const int* in_sizes, int n_in,
                              void* d_out, int out_size) {
    const float* dense  = (const float*)d_in[0];   // [16384, 128] fp32
    const float* sparse = (const float*)d_in[1];   // [16384, 26, 128] fp32
    float* out = (float*)d_out;                    // [16384, 479] fp32

    cudaFuncSetAttribute(dlrm_interact_kernel,
                         cudaFuncAttributeMaxDynamicSharedMemorySize, SMEM_BYTES);
    dlrm_interact_kernel<<<BATCH / SAMPLES, THREADS, SMEM_BYTES>>>(dense, sparse, out);
}

// round 10
// speedup vs baseline: 2.4661x; 1.6307x over previous
#include <cuda_runtime.h>
#include <cstdint>

#define BATCH   16384
#define NF      27            // 1 dense + 26 sparse rows
#define OUTW    479           // 128 + 351
#define WPC     8             // warps (= samples) per CTA
#define THREADS 256
#define WBUF    8704          // bytes of private buffer per warp
#define SMEM_BYTES (WPC * WBUF)   // 69632

__device__ __forceinline__ uint32_t smem_u32(const void* p) {
    uint32_t a;
    asm("{ .reg .u64 t; cvta.to.shared.u64 t, %1; cvt.u32.u64 %0, t; }" : "=r"(a) : "l"(p));
    return a;
}
__device__ __forceinline__ void ldm4(uint32_t r[4], uint32_t addr) {
    asm volatile("ldmatrix.sync.aligned.m8n8.x4.shared.b16 {%0,%1,%2,%3}, [%4];"
                 : "=r"(r[0]), "=r"(r[1]), "=r"(r[2]), "=r"(r[3]) : "r"(addr));
}
__device__ __forceinline__ void mma16816(float d[4], const uint32_t a[4], const uint32_t b[2]) {
    asm volatile(
        "mma.sync.aligned.m16n8k16.row.col.f32.bf16.bf16.f32 "
        "{%0,%1,%2,%3}, {%4,%5,%6,%7}, {%8,%9}, {%0,%1,%2,%3};"
        : "+f"(d[0]), "+f"(d[1]), "+f"(d[2]), "+f"(d[3])
        : "r"(a[0]), "r"(a[1]), "r"(a[2]), "r"(a[3]), "r"(b[0]), "r"(b[1]));
}
__device__ __forceinline__ void sts2(uint32_t addr, float x, float y) {
    asm volatile("st.shared.v2.b32 [%0], {%1,%2};"
                 :: "r"(addr), "r"(__float_as_uint(x)), "r"(__float_as_uint(y)));
}
__device__ __forceinline__ float lds1(uint32_t addr) {
    float v;
    asm volatile("ld.shared.f32 %0, [%1];" : "=f"(v) : "r"(addr));
    return v;
}

// Buffer layout per warp (one K-half at a time):
//   H: rows 0..31  (row = feature f; 64 bf16 = 128 B/row), bytes [0, 4096)
//   L: rows 0..31  at +4096
// Swizzle: 16B chunk q of row r stored at chunk (q ^ (r & 7)).
// Epilogue overlay: P at [0, 4352) stride-34 rows, Q at [4352, 8704).

__global__ __launch_bounds__(THREADS, 2)
void dlrm_mma_kernel(const float* __restrict__ dense,
                     const float* __restrict__ sparse,
                     float* __restrict__ out) {
    extern __shared__ __align__(128) char smem[];
    const int tid  = threadIdx.x;
    const int w    = tid >> 5;
    const int lane = tid & 31;
    const int b    = blockIdx.x * WPC + w;
    const uint32_t buf = smem_u32(smem) + w * WBUF;

    // per-lane constants
    const int cl  = lane & 15, r2 = lane >> 4;              // load mapping
    const int rowA = (lane & 7) + ((lane >> 3) & 1) * 8;    // A-frag row (+ mt*16)
    const int qsA  = (lane >> 4) & 1;                        // A-frag k-chunk select
    const int rowB = (lane & 7) + ((lane >> 4) & 1) * 8;    // B-frag row (+ nt*16)
    const int qsB  = (lane >> 3) & 1;

    float accP[6][4], accQ[8][4];
#pragma unroll
    for (int t = 0; t < 6; t++)
#pragma unroll
        for (int i = 0; i < 4; i++) accP[t][i] = 0.f;
#pragma unroll
    for (int t = 0; t < 8; t++)
#pragma unroll
        for (int i = 0; i < 4; i++) accQ[t][i] = 0.f;

#pragma unroll
    for (int half = 0; half < 2; half++) {
        // ---- load + bf16 split (warp loads its own sample's K-half) ----
        const int gchunk = half * 16 + cl;      // float4 index within the 128-f row
#pragma unroll
        for (int it = 0; it < 14; it++) {
            const int f = it * 2 + r2;
            if (f < NF) {
                float4 v = (f == 0)
                    ? reinterpret_cast<const float4*>(dense)[b * 32 + gchunk]
                    : reinterpret_cast<const float4*>(sparse)[(b * 26 + (f - 1)) * 32 + gchunk];
                if (f == 0) {                    // dense passthrough
                    float* o = out + (size_t)b * OUTW + (gchunk << 2);
                    o[0] = v.x; o[1] = v.y; o[2] = v.z; o[3] = v.w;
                }
                uint32_t h01, h23, l01, l23;
                asm("cvt.rn.bf16x2.f32 %0, %1, %2;" : "=r"(h01) : "f"(v.y), "f"(v.x));
                asm("cvt.rn.bf16x2.f32 %0, %1, %2;" : "=r"(h23) : "f"(v.w), "f"(v.z));
                float s0 = v.x - __uint_as_float(h01 << 16);
                float s1 = v.y - __uint_as_float(h01 & 0xFFFF0000u);
                float s2 = v.z - __uint_as_float(h23 << 16);
                float s3 = v.w - __uint_as_float(h23 & 0xFFFF0000u);
                asm("cvt.rn.bf16x2.f32 %0, %1, %2;" : "=r"(l01) : "f"(s1), "f"(s0));
                asm("cvt.rn.bf16x2.f32 %0, %1, %2;" : "=r"(l23) : "f"(s3), "f"(s2));
                const uint32_t off = buf + f * 128
                                   + ((((cl >> 1) ^ (f & 7))) << 4) + ((cl & 1) << 3);
                asm volatile("st.shared.v2.b32 [%0], {%1,%2};" :: "r"(off), "r"(h01), "r"(h23));
                asm volatile("st.shared.v2.b32 [%0], {%1,%2};" :: "r"(off + 4096), "r"(l01), "r"(l23));
            }
        }
        __syncwarp();

        // ---- 4 K-steps of m16n8k16 over this half ----
#pragma unroll
        for (int k = 0; k < 4; k++) {
            const int qA = (k * 2 + qsA) ^ (rowA & 7);
            const int qB = (k * 2 + qsB) ^ (rowB & 7);
            const uint32_t aA0 = buf + rowA * 128 + (qA << 4);        // H rows 0-15
            const uint32_t aB0 = buf + rowB * 128 + (qB << 4);        // H rows 0-15 (as B)
            uint32_t a0[4], a1[4], bh0[4], bh1[4], bl0[4], bl1[4];
            ldm4(a0, aA0);           ldm4(a1, aA0 + 2048);            // H rows 16-31
            ldm4(bh0, aB0);          ldm4(bh1, aB0 + 2048);
            ldm4(bl0, aB0 + 4096);   ldm4(bl1, aB0 + 6144);           // L
            // P = H·H^T (upper tiles only)
            mma16816(accP[0], a0, bh0);     mma16816(accP[1], a0, bh0 + 2);
            mma16816(accP[2], a0, bh1);     mma16816(accP[3], a0, bh1 + 2);
            mma16816(accP[4], a1, bh1);     mma16816(accP[5], a1, bh1 + 2);
            // Q = H·L^T (full)
            mma16816(accQ[0], a0, bl0);     mma16816(accQ[1], a0, bl0 + 2);
            mma16816(accQ[2], a0, bl1);     mma16816(accQ[3], a0, bl1 + 2);
            mma16816(accQ[4], a1, bl0);     mma16816(accQ[5], a1, bl0 + 2);
            mma16816(accQ[6], a1, bl1);     mma16816(accQ[7], a1, bl1 + 2);
        }
        __syncwarp();
    }

    // ---- epilogue: stage P,Q into dead buffer (stride-34 rows), gather triu ----
    const int rr = lane >> 2, cc = (lane & 3) * 2;
    {
        const int pmt[6] = {0, 0, 0, 0, 1, 1};
        const int pnt[6] = {0, 1, 2, 3, 2, 3};
#pragma unroll
        for (int t = 0; t < 6; t++) {
            const uint32_t ad = buf + (((pmt[t] * 16 + rr) * 34 + pnt[t] * 8 + cc) << 2);
            sts2(ad,            accP[t][0], accP[t][1]);
            sts2(ad + 8 * 136,  accP[t][2], accP[t][3]);   // +8 rows
        }
#pragma unroll
        for (int t = 0; t < 8; t++) {
            const int mt = t >> 2, nt = t & 3;
            const uint32_t ad = buf + 4352 + (((mt * 16 + rr) * 34 + nt * 8 + cc) << 2);
            sts2(ad,            accQ[t][0], accQ[t][1]);
            sts2(ad + 8 * 136,  accQ[t][2], accQ[t][3]);
        }
    }
    __syncwarp();

    float* orow = out + (size_t)b * OUTW + 128;
#pragma unroll
    for (int t = 0; t < 11; t++) {
        const int p = lane + t * 32;
        if (p < 351) {
            // invert p -> (i, j) of triu_indices(27, k=1): S(i) = i*(53-i)/2
            int i = (int)((53.0f - sqrtf((float)(2809 - 8 * p))) * 0.5f);
            if (i > 0 && p < (i * (53 - i)) / 2) i--;
            if (p >= ((i + 1) * (52 - i)) / 2) i++;
            const int j = i + 1 + (p - (i * (53 - i)) / 2);
            const float pij = lds1(buf + ((i * 34 + j) << 2));
            const float qij = lds1(buf + 4352 + ((i * 34 + j) << 2));
            const float qji = lds1(buf + 4352 + ((j * 34 + i) << 2));
            orow[p] = pij + qij + qji;
        }
    }
}

extern "C" void kernel_launch(void* const* d_in, const int* in_sizes, int n_in,
                              void* d_out, int out_size) {
    const float* dense  = (const float*)d_in[0];   // [16384, 128] fp32
    const float* sparse = (const float*)d_in[1];   // [16384, 26, 128] fp32
    float* out = (float*)d_out;                    // [16384, 479] fp32

    cudaFuncSetAttribute(dlrm_mma_kernel,
                         cudaFuncAttributeMaxDynamicSharedMemorySize, SMEM_BYTES);
    dlrm_mma_kernel<<<BATCH / WPC, THREADS, SMEM_BYTES>>>(dense, sparse, out);
}

// round 11
// speedup vs baseline: 2.8191x; 1.1432x over previous
#include <cuda_runtime.h>
#include <cstdint>

#define BATCH   16384
#define NF      27            // 1 dense + 26 sparse rows
#define OUTW    479           // 128 + 351
#define WPC     8             // warps (= samples) per CTA
#define THREADS 256
#define WBUF    8192          // bytes per warp: H[32x64bf16]=4K + L=4K (epilogue overlays)
#define SMEM_BYTES (WPC * WBUF)   // 65536 -> 3 CTAs/SM

__device__ __forceinline__ uint32_t smem_u32(const void* p) {
    uint32_t a;
    asm("{ .reg .u64 t; cvta.to.shared.u64 t, %1; cvt.u32.u64 %0, t; }" : "=r"(a) : "l"(p));
    return a;
}
__device__ __forceinline__ void ldm4(uint32_t r[4], uint32_t addr) {
    asm volatile("ldmatrix.sync.aligned.m8n8.x4.shared.b16 {%0,%1,%2,%3}, [%4];"
                 : "=r"(r[0]), "=r"(r[1]), "=r"(r[2]), "=r"(r[3]) : "r"(addr));
}
__device__ __forceinline__ void mma16816(float d[4], const uint32_t a[4], const uint32_t b[2]) {
    asm volatile(
        "mma.sync.aligned.m16n8k16.row.col.f32.bf16.bf16.f32 "
        "{%0,%1,%2,%3}, {%4,%5,%6,%7}, {%8,%9}, {%0,%1,%2,%3};"
        : "+f"(d[0]), "+f"(d[1]), "+f"(d[2]), "+f"(d[3])
        : "r"(a[0]), "r"(a[1]), "r"(a[2]), "r"(a[3]), "r"(b[0]), "r"(b[1]));
}
__device__ __forceinline__ void sts2(uint32_t addr, float x, float y) {
    asm volatile("st.shared.v2.b32 [%0], {%1,%2};"
                 :: "r"(addr), "r"(__float_as_uint(x)), "r"(__float_as_uint(y)));
}
__device__ __forceinline__ float lds1(uint32_t addr) {
    float v;
    asm volatile("ld.shared.f32 %0, [%1];" : "=f"(v) : "r"(addr));
    return v;
}

// Per-warp buffer (one K-half at a time):
//   H rows 0..31 (row = feature; 64 bf16 = 128 B/row) at [0, 4096)
//   L rows 0..31 at [4096, 8192)
// Swizzle: 16B chunk q of row r stored at chunk (q ^ (r & 7)) -> conflict-free ldmatrix.
// Epilogue overlay: G upper 32x32, stride 34 floats, at [0, 4352).

__global__ __launch_bounds__(THREADS, 3)
void dlrm_mma_kernel(const float* __restrict__ dense,
                     const float* __restrict__ sparse,
                     float* __restrict__ out) {
    extern __shared__ __align__(128) char smem[];
    const int tid  = threadIdx.x;
    const int w    = tid >> 5;
    const int lane = tid & 31;
    const int b    = blockIdx.x * WPC + w;
    const uint32_t buf = smem_u32(smem) + w * WBUF;

    // per-lane constants
    const int cl  = lane & 15, r2 = lane >> 4;              // load mapping
    const int rowA = (lane & 7) + ((lane >> 3) & 1) * 8;    // ldmatrix A row (+ mt*16)
    const int qsA  = (lane >> 4) & 1;                        // A k-chunk select
    const int rowB = (lane & 7) + ((lane >> 4) & 1) * 8;    // ldmatrix B row (+ nt*16)
    const int qsB  = (lane >> 3) & 1;

    // G upper tiles: (mt,nt) in {(0,0),(0,1),(0,2),(0,3),(1,2),(1,3)}; 16x8 each
    float acc[6][4];
#pragma unroll
    for (int t = 0; t < 6; t++)
#pragma unroll
        for (int i = 0; i < 4; i++) acc[t][i] = 0.f;

#pragma unroll
    for (int half = 0; half < 2; half++) {
        // ---- load + bf16 split (warp loads its own sample's K-half) ----
        const int gchunk = half * 16 + cl;      // float4 index within the 128-f row
#pragma unroll
        for (int it = 0; it < 14; it++) {
            const int f = it * 2 + r2;
            if (f < NF) {
                float4 v = (f == 0)
                    ? reinterpret_cast<const float4*>(dense)[b * 32 + gchunk]
                    : reinterpret_cast<const float4*>(sparse)[(b * 26 + (f - 1)) * 32 + gchunk];
                if (f == 0) {                    // dense passthrough
                    float* o = out + (size_t)b * OUTW + (gchunk << 2);
                    o[0] = v.x; o[1] = v.y; o[2] = v.z; o[3] = v.w;
                }
                uint32_t h01, h23, l01, l23;
                asm("cvt.rn.bf16x2.f32 %0, %1, %2;" : "=r"(h01) : "f"(v.y), "f"(v.x));
                asm("cvt.rn.bf16x2.f32 %0, %1, %2;" : "=r"(h23) : "f"(v.w), "f"(v.z));
                float s0 = v.x - __uint_as_float(h01 << 16);
                float s1 = v.y - __uint_as_float(h01 & 0xFFFF0000u);
                float s2 = v.z - __uint_as_float(h23 << 16);
                float s3 = v.w - __uint_as_float(h23 & 0xFFFF0000u);
                asm("cvt.rn.bf16x2.f32 %0, %1, %2;" : "=r"(l01) : "f"(s1), "f"(s0));
                asm("cvt.rn.bf16x2.f32 %0, %1, %2;" : "=r"(l23) : "f"(s3), "f"(s2));
                const uint32_t off = buf + f * 128
                                   + ((((cl >> 1) ^ (f & 7))) << 4) + ((cl & 1) << 3);
                asm volatile("st.shared.v2.b32 [%0], {%1,%2};" :: "r"(off), "r"(h01), "r"(h23));
                asm volatile("st.shared.v2.b32 [%0], {%1,%2};" :: "r"(off + 4096), "r"(l01), "r"(l23));
            }
        }
        __syncwarp();

        // ---- 4 K-steps of m16n8k16; G = H·H^T + H·L^T + L·H^T on upper tiles ----
#pragma unroll
        for (int k = 0; k < 4; k++) {
            const int qA = (k * 2 + qsA) ^ (rowA & 7);
            const int qB = (k * 2 + qsB) ^ (rowB & 7);
            const uint32_t pA = buf + rowA * 128 + (qA << 4);
            const uint32_t pB = buf + rowB * 128 + (qB << 4);
            uint32_t aH0[4], aH1[4], aL0[4], aL1[4];
            uint32_t bH0[4], bH1[4], bL0[4], bL1[4];
            ldm4(aH0, pA);          ldm4(aH1, pA + 2048);    // H rows 0-15 / 16-31 (A)
            ldm4(aL0, pA + 4096);   ldm4(aL1, pA + 6144);    // L (A)
            ldm4(bH0, pB);          ldm4(bH1, pB + 2048);    // H n 0-15 / 16-31 (B)
            ldm4(bL0, pB + 4096);   ldm4(bL1, pB + 6144);    // L (B)
            // tile t: mt = (t>=4), nt = t<4 ? t : t-2
            mma16816(acc[0], aH0, bH0);      mma16816(acc[0], aH0, bL0);      mma16816(acc[0], aL0, bH0);
            mma16816(acc[1], aH0, bH0 + 2);  mma16816(acc[1], aH0, bL0 + 2);  mma16816(acc[1], aL0, bH0 + 2);
            mma16816(acc[2], aH0, bH1);      mma16816(acc[2], aH0, bL1);      mma16816(acc[2], aL0, bH1);
            mma16816(acc[3], aH0, bH1 + 2);  mma16816(acc[3], aH0, bL1 + 2);  mma16816(acc[3], aL0, bH1 + 2);
            mma16816(acc[4], aH1, bH1);      mma16816(acc[4], aH1, bL1);      mma16816(acc[4], aL1, bH1);
            mma16816(acc[5], aH1, bH1 + 2);  mma16816(acc[5], aH1, bL1 + 2);  mma16816(acc[5], aL1, bH1 + 2);
        }
        __syncwarp();
    }

    // ---- epilogue: stage 6 G tiles into dead buffer (stride 34), gather triu ----
    {
        const int rr = lane >> 2, cc = (lane & 3) * 2;
        const int pmt[6] = {0, 0, 0, 0, 1, 1};
        const int pnt[6] = {0, 1, 2, 3, 2, 3};
#pragma unroll
        for (int t = 0; t < 6; t++) {
            const uint32_t ad = buf + (((pmt[t] * 16 + rr) * 34 + pnt[t] * 8 + cc) << 2);
            sts2(ad,           acc[t][0], acc[t][1]);
            sts2(ad + 8 * 136, acc[t][2], acc[t][3]);   // +8 rows
        }
    }
    __syncwarp();

    float* orow = out + (size_t)b * OUTW + 128;
#pragma unroll
    for (int t = 0; t < 11; t++) {
        const int p = lane + t * 32;
        if (p < 351) {
            // invert p -> (i, j) of triu_indices(27, k=1): S(i) = i*(53-i)/2
            int i = (int)((53.0f - sqrtf((float)(2809 - 8 * p))) * 0.5f);
            if (i > 0 && p < (i * (53 - i)) / 2) i--;
            if (p >= ((i + 1) * (52 - i)) / 2) i++;
            const int j = i + 1 + (p - (i * (53 - i)) / 2);
            orow[p] = lds1(buf + ((i * 34 + j) << 2));
        }
    }
}

extern "C" void kernel_launch(void* const* d_in, const int* in_sizes, int n_in,
                              void* d_out, int out_size) {
    const float* dense  = (const float*)d_in[0];   // [16384, 128] fp32
    const float* sparse = (const float*)d_in[1];   // [16384, 26, 128] fp32
    float* out = (float*)d_out;                    // [16384, 479] fp32

    cudaFuncSetAttribute(dlrm_mma_kernel,
                         cudaFuncAttributeMaxDynamicSharedMemorySize, SMEM_BYTES);
    dlrm_mma_kernel<<<BATCH / WPC, THREADS, SMEM_BYTES>>>(dense, sparse, out);
}